// round 8
// baseline (speedup 1.0000x reference)
#include <cuda_runtime.h>
#include <cstdint>

// HashTables: rolling xor-hash over prefix windows {1,2,4,...,128}, then gather
// 8 embedding rows (64 f32 each) per (b,t) into out[b][t][8*64].
//
// Proven-exact math (R2+): BUCKETS = 2^19 so h % BUCKETS == h & 0x7FFFF and
// only the low 32 bits of token*prime matter -> pure u32 arithmetic. Zero
// tokens XOR as no-ops, so the t-1-j < 0 boundary is a zero-padded smem halo.
//
// R7 -> R8 ROOT CAUSE: R4/R5/R7 all used NTHR=128 with a 144-entry token tile
// staged by `if (tid < 144)` -> s_tok[128..143] (the most-recent tokens) were
// never initialized. Not an async race. Fixed with a strided staging loop.
// Architecture unchanged from R7: 2048 fire-and-forget cp.async.cg 16B
// gathers per block stage rows into smem in output byte order (~192KB reads
// in flight per SM), then one coalesced smem->global .cs writeback.

#define T_LEN   4096
#define B_ROWS  8
#define P_TILE  16
#define NTHR    128
#define HALO    128
#define MASK19  0x7FFFFu
#define ROWS_PER_BLK (P_TILE * 8)             // 128 rows
#define STAGE_BYTES  (ROWS_PER_BLK * 256)     // 32 KB

static __device__ __forceinline__ unsigned prime_of(int j) {
    const unsigned PR[8] = {2654435761u, 2246822519u, 3266489917u, 2028178513u,
                            1220703125u, 1610612741u, 805306457u, 402653189u};
    return PR[j & 7];
}

static __device__ __forceinline__ unsigned smem_u32(const void* p) {
    return (unsigned)__cvta_generic_to_shared(p);
}

static __device__ __forceinline__ void stg_cs_f4(float4* p, float4 v) {
    asm volatile("st.global.cs.v4.f32 [%0], {%1, %2, %3, %4};"
                 :: "l"(p), "f"(v.x), "f"(v.y), "f"(v.z), "f"(v.w) : "memory");
}

__global__ __launch_bounds__(NTHR)
void hash_gather_kernel(const int* __restrict__ tokens,         // [B][T] int32
                        const float* __restrict__ tables,       // [8][2^19][64] f32
                        float* __restrict__ out)                // [B][T][512] f32
{
    __shared__ alignas(16) unsigned char s_stage[STAGE_BYTES];
    __shared__ unsigned s_tok[P_TILE + HALO];   // 144 u32
    __shared__ unsigned s_idx[ROWS_PER_BLK];    // s_idx[p*8 + tbl]

    const int tid = threadIdx.x;
    const int b   = blockIdx.y;
    const int t0  = blockIdx.x * P_TILE;

    // ---- Phase 0: stage tokens (STRIDED: 144 slots > 128 threads),
    //      zero-pad before row start ----
    for (int i = tid; i < P_TILE + HALO; i += NTHR) {
        int g = t0 - HALO + i;
        s_tok[i] = (g >= 0) ? (unsigned)tokens[(size_t)b * T_LEN + g] : 0u;
    }
    __syncthreads();

    // ---- Phase 1: rolling hash, snapshot at each power-of-two window ----
    if (tid < P_TILE) {
        unsigned h = 0;
        int w = 0;
        #pragma unroll
        for (int j = 0; j < 128; j++) {
            h ^= s_tok[tid + (HALO - 1) - j] * prime_of(j);
            const int off = j + 1;
            if ((off & (off - 1)) == 0) {       // off in {1,2,4,...,128}
                s_idx[tid * 8 + w] = h & MASK19;
                w++;
            }
        }
    }
    __syncthreads();

    // ---- Phase 2: 16 async 16B gathers per thread into the stage buffer.
    // Element e = (row r = e>>4, f4 = e&15); row r = (p<<3)+tbl; stage layout
    // e*16 bytes == output byte order. 16 consecutive threads cover one
    // contiguous 256B table row.
    {
        const char* __restrict__ tabb = (const char*)tables;
        const unsigned stage0 = smem_u32(s_stage);
        #pragma unroll
        for (int k = 0; k < 16; k++) {
            const int e  = tid + NTHR * k;
            const int r  = e >> 4;
            const int f4 = e & 15;
            const char* src = tabb +
                ((((size_t)(r & 7) << 19) + s_idx[r]) << 8) + (f4 << 4);
            const unsigned dst = stage0 + (e << 4);
            asm volatile("cp.async.cg.shared.global [%0], [%1], 16;"
                         :: "r"(dst), "l"(src) : "memory");
        }
        asm volatile("cp.async.commit_group;" ::: "memory");
        asm volatile("cp.async.wait_group 0;" ::: "memory");
    }
    __syncthreads();

    // ---- Phase 3: coalesced writeback, evict-first stores ----
    {
        float4* __restrict__ ob =
            (float4*)out + (((size_t)b * T_LEN + t0) << 7);
        const float4* __restrict__ st4 = (const float4*)s_stage;
        #pragma unroll
        for (int k = 0; k < 16; k++) {
            const int e = tid + NTHR * k;
            stg_cs_f4(ob + e, st4[e]);
        }
    }
}

extern "C" void kernel_launch(void* const* d_in, const int* in_sizes, int n_in,
                              void* d_out, int out_size) {
    const int* tokens   = (const int*)d_in[0];
    const float* tables = (const float*)d_in[1];
    float* out          = (float*)d_out;

    dim3 grid(T_LEN / P_TILE, B_ROWS);   // (256, 8) = 2048 blocks
    hash_gather_kernel<<<grid, NTHR>>>(tokens, tables, out);
}

// round 9
// speedup vs baseline: 1.2162x; 1.2162x over previous
#include <cuda_runtime.h>

// HashTables: rolling xor-hash over prefix windows {1,2,4,...,128}, then gather
// 8 embedding rows (64 f32 each) per (b,t) into out[b][t][8*64].
//
// Proven-exact math (R2+): BUCKETS = 2^19 so h % BUCKETS == h & 0x7FFFF and
// only the low 32 bits of token*prime matter -> pure u32 arithmetic. Zero
// tokens XOR as no-ops, so the t-1-j < 0 boundary is a zero-padded smem halo.
//
// R8 -> R9: gather reverts to the proven R3 shape (best: 18.9us, near the
// practical HBM ceiling for 128MB mixed random-read/stream-write). New lever:
// Phase-1 hash parallelized 8x. Term j uses prime PR[j%8], so lane l of each
// position accumulates only j = l (mod 8) -- a 16-step chain with one constant
// prime -- snapshotting after 1,2,4,8,16 own-terms. Window 2^w (w>=3) = XOR of
// the 8 lanes' c_{2^(w-3)}; windows 1,2,4 = XOR of first terms of lanes l<W.
// All 256 threads active; per-block hash critical path drops ~8x.

#define T_LEN   4096
#define B_ROWS  8
#define P_TILE  32          // t-positions per block
#define NTHR    256
#define HALO    128
#define MASK19  0x7FFFFu

static __device__ __forceinline__ void stg_cs_f4(float4* p, float4 v) {
    asm volatile("st.global.cs.v4.f32 [%0], {%1, %2, %3, %4};"
                 :: "l"(p), "f"(v.x), "f"(v.y), "f"(v.z), "f"(v.w) : "memory");
}

__global__ __launch_bounds__(NTHR)
void hash_gather_kernel(const int* __restrict__ tokens,         // [B][T] int32
                        const float* __restrict__ tables,       // [8][2^19][64] f32
                        float* __restrict__ out)                // [B][T][512] f32
{
    __shared__ unsigned s_tok[P_TILE + HALO];   // 160 u32
    __shared__ unsigned s_part[P_TILE * 8 * 5]; // c_{1,2,4,8,16} per (pos,lane)
    __shared__ unsigned s_idx[P_TILE * 8];      // bucket ids per (pos, window)

    const unsigned PR[8] = {2654435761u, 2246822519u, 3266489917u, 2028178513u,
                            1220703125u, 1610612741u, 805306457u, 402653189u};

    const int tid = threadIdx.x;
    const int b  = blockIdx.y;
    const int t0 = blockIdx.x * P_TILE;

    // ---- Phase 0: stage tokens, zero-pad before row start ----
    if (tid < P_TILE + HALO) {
        int g = t0 - HALO + tid;
        s_tok[tid] = (g >= 0) ? (unsigned)tokens[(size_t)b * T_LEN + g] : 0u;
    }
    __syncthreads();

    // ---- Phase 1a: per-(pos,lane) partial hash, 16-step chain ----
    {
        const int p = tid >> 3;         // position 0..31
        const int l = tid & 7;          // lane (= j mod 8)
        const unsigned prime = PR[l];
        unsigned* dst = &s_part[(size_t)tid * 5];
        unsigned h = 0;
        int w = 0;
        #pragma unroll
        for (int m = 0; m < 16; m++) {
            // j = l + 8m; token local index p + 127 - j
            h ^= s_tok[p + (HALO - 1) - (l + 8 * m)] * prime;
            const int cnt = m + 1;
            if ((cnt & (cnt - 1)) == 0) {   // cnt in {1,2,4,8,16}
                dst[w] = h;
                w++;
            }
        }
    }
    __syncthreads();

    // ---- Phase 1b: reduce 8 lanes per (pos, window) ----
    {
        const int p = tid >> 3;         // position
        const int w = tid & 7;          // window index, W = 2^w
        const unsigned* base = &s_part[(size_t)p * 40];
        unsigned h = 0;
        if (w >= 3) {
            const int k = w - 3;        // use c_{2^k}
            #pragma unroll
            for (int l = 0; l < 8; l++) h ^= base[l * 5 + k];
        } else {
            const int W = 1 << w;       // 1, 2, or 4 lanes, first term each
            for (int l = 0; l < W; l++) h ^= base[l * 5 + 0];
        }
        s_idx[tid] = h & MASK19;        // s_idx[p*8 + w]
    }
    __syncthreads();

    // ---- Phase 2: gather + write (proven R3 shape) ----
    const size_t out_base_f4 = ((size_t)b * T_LEN + t0) << 7;   // *128 f4/pos
    const float4* __restrict__ tab4 = (const float4*)tables;
    float4* __restrict__ out4 = (float4*)out;

    #pragma unroll 4
    for (int e = tid; e < P_TILE * 128; e += NTHR) {
        const int rest = e & 127;       // within-position element
        const int p    = e >> 7;        // local position
        const int tbl  = rest >> 4;     // table id 0..7
        const int f4   = rest & 15;     // float4 within 64-float row
        const unsigned idx = s_idx[p * 8 + tbl];
        const float4 v = __ldg(tab4 + ((((size_t)tbl << 19) + idx) << 4) + f4);
        stg_cs_f4(out4 + out_base_f4 + e, v);
    }
}

extern "C" void kernel_launch(void* const* d_in, const int* in_sizes, int n_in,
                              void* d_out, int out_size) {
    const int* tokens   = (const int*)d_in[0];
    const float* tables = (const float*)d_in[1];
    float* out          = (float*)d_out;

    dim3 grid(T_LEN / P_TILE, B_ROWS);   // (128, 8) = 1024 blocks
    hash_gather_kernel<<<grid, NTHR>>>(tokens, tables, out);
}

// round 10
// speedup vs baseline: 1.2183x; 1.0017x over previous
#include <cuda_runtime.h>

// HashTables: rolling xor-hash over prefix windows {1,2,4,...,128}, then gather
// 8 embedding rows (64 f32 each) per (b,t) into out[b][t][8*64].
//
// Proven-exact math (R2+): BUCKETS = 2^19 so h % BUCKETS == h & 0x7FFFF and
// only the low 32 bits of token*prime matter -> pure u32 arithmetic. Zero
// tokens XOR as no-ops, so the t-1-j < 0 boundary is a zero-padded smem halo.
//
// R9 -> R10: TLB hypothesis. Tables span 256 x 2MB pages vs a 128-entry TLB;
// previous designs kept all 8 tables live per SM at every instant (thread's
// table id was a function of tid) -> ~256-page random working set -> PTW
// stream as the invariant ceiling (DRAM stuck at 43% across three designs).
// Fix: phase the gather by table -- iteration k gathers ONLY table k>>1, so
// the instantaneous working set is one table = 32 pages (TLB-resident).
// Loads stay 256B-contiguous per 16-thread group; stores are 256B chunks at
// 2KB stride (fully coalesced). Hash phases unchanged from passing R9.

#define T_LEN   4096
#define B_ROWS  8
#define P_TILE  32          // t-positions per block
#define NTHR    256
#define HALO    128
#define MASK19  0x7FFFFu

static __device__ __forceinline__ void stg_cs_f4(float4* p, float4 v) {
    asm volatile("st.global.cs.v4.f32 [%0], {%1, %2, %3, %4};"
                 :: "l"(p), "f"(v.x), "f"(v.y), "f"(v.z), "f"(v.w) : "memory");
}

__global__ __launch_bounds__(NTHR)
void hash_gather_kernel(const int* __restrict__ tokens,         // [B][T] int32
                        const float* __restrict__ tables,       // [8][2^19][64] f32
                        float* __restrict__ out)                // [B][T][512] f32
{
    __shared__ unsigned s_tok[P_TILE + HALO];   // 160 u32
    __shared__ unsigned s_part[P_TILE * 8 * 5]; // c_{1,2,4,8,16} per (pos,lane)
    __shared__ unsigned s_idx[P_TILE * 8];      // bucket ids per (pos, window)

    const unsigned PR[8] = {2654435761u, 2246822519u, 3266489917u, 2028178513u,
                            1220703125u, 1610612741u, 805306457u, 402653189u};

    const int tid = threadIdx.x;
    const int b  = blockIdx.y;
    const int t0 = blockIdx.x * P_TILE;

    // ---- Phase 0: stage tokens, zero-pad before row start ----
    if (tid < P_TILE + HALO) {
        int g = t0 - HALO + tid;
        s_tok[tid] = (g >= 0) ? (unsigned)tokens[(size_t)b * T_LEN + g] : 0u;
    }
    __syncthreads();

    // ---- Phase 1a: per-(pos,lane) partial hash, 16-step chain ----
    {
        const int p = tid >> 3;         // position 0..31
        const int l = tid & 7;          // lane (= j mod 8)
        const unsigned prime = PR[l];
        unsigned* dst = &s_part[(size_t)tid * 5];
        unsigned h = 0;
        int w = 0;
        #pragma unroll
        for (int m = 0; m < 16; m++) {
            // j = l + 8m; token local index p + 127 - j
            h ^= s_tok[p + (HALO - 1) - (l + 8 * m)] * prime;
            const int cnt = m + 1;
            if ((cnt & (cnt - 1)) == 0) {   // cnt in {1,2,4,8,16}
                dst[w] = h;
                w++;
            }
        }
    }
    __syncthreads();

    // ---- Phase 1b: reduce 8 lanes per (pos, window) ----
    {
        const int p = tid >> 3;         // position
        const int w = tid & 7;          // window index, W = 2^w
        const unsigned* base = &s_part[(size_t)p * 40];
        unsigned h = 0;
        if (w >= 3) {
            const int k = w - 3;        // use c_{2^k}
            #pragma unroll
            for (int l = 0; l < 8; l++) h ^= base[l * 5 + k];
        } else {
            const int W = 1 << w;       // 1, 2, or 4 lanes, first term each
            for (int l = 0; l < W; l++) h ^= base[l * 5 + 0];
        }
        s_idx[tid] = h & MASK19;        // s_idx[p*8 + w]
    }
    __syncthreads();

    // ---- Phase 2: TABLE-PHASED gather + write. Iteration k touches only
    // table k>>1: block-wide (and roughly GPU-wide) page working set is one
    // table (32 x 2MB pages) at a time.
    const size_t out_base_f4 = ((size_t)b * T_LEN + t0) << 7;   // *128 f4/pos
    const float4* __restrict__ tab4 = (const float4*)tables;
    float4* __restrict__ out4 = (float4*)out;

    const int rowg = tid >> 4;          // 0..15: row slot within iteration
    const int f4   = tid & 15;          // float4 within 64-float row

    #pragma unroll
    for (int k = 0; k < 16; k++) {
        const int tbl = k >> 1;                     // one table per 2 iters
        const int p   = ((k & 1) << 4) + rowg;      // position 0..31
        const unsigned idx = s_idx[p * 8 + tbl];
        const float4 v = __ldg(tab4 + ((((size_t)tbl << 19) + idx) << 4) + f4);
        stg_cs_f4(out4 + out_base_f4 + (((size_t)((p << 3) + tbl)) << 4) + f4, v);
    }
}

extern "C" void kernel_launch(void* const* d_in, const int* in_sizes, int n_in,
                              void* d_out, int out_size) {
    const int* tokens   = (const int*)d_in[0];
    const float* tables = (const float*)d_in[1];
    float* out          = (float*)d_out;

    dim3 grid(T_LEN / P_TILE, B_ROWS);   // (128, 8) = 1024 blocks
    hash_gather_kernel<<<grid, NTHR>>>(tokens, tables, out);
}